// round 2
// baseline (speedup 1.0000x reference)
#include <cuda_runtime.h>

#define PL_TOTAL (2048 * 256)   // 524288 occurrences
#define NNODES   50000
#define DIM      256

// Scratch (static device globals -- no allocation in kernel_launch)
__device__ float g_q[(size_t)NNODES * DIM];
__device__ float g_agg[(size_t)NNODES * DIM];
__device__ float g_denom[NNODES];
__device__ int   g_mask_word;   // 1 = mask elements are 4-byte (f32/i32), 0 = 1-byte

// ---------------------------------------------------------------------------
// Detect mask element width from raw bytes (deterministic).
//   float32 1.0f = 00 00 80 3F  -> 0x3F at byte offset %4==3
//   int32   1    = 01 00 00 00  -> nonzero only at offset %4==0
//   uint8   1    = 01           -> nonzero at arbitrary offsets, never 0x3F
// ---------------------------------------------------------------------------
__global__ void detect_mask_kernel(const unsigned char* __restrict__ m) {
    __shared__ int f32flag, oddflag;
    if (threadIdx.x == 0) { f32flag = 0; oddflag = 0; }
    __syncthreads();
    for (int i = threadIdx.x; i < 4096; i += blockDim.x) {
        unsigned char b = m[i];
        if (b == 0x3F && (i & 3) == 3) atomicOr(&f32flag, 1);
        if (b != 0 && (i & 3) != 0)    atomicOr(&oddflag, 1);
    }
    __syncthreads();
    if (threadIdx.x == 0)
        g_mask_word = (f32flag || !oddflag) ? 1 : 0;
}

// ---------------------------------------------------------------------------
// Zero the accumulators
// ---------------------------------------------------------------------------
__global__ void zero_kernel() {
    size_t i = (size_t)blockIdx.x * blockDim.x + threadIdx.x;
    size_t stride = (size_t)gridDim.x * blockDim.x;
    size_t total = (size_t)NNODES * DIM;
    for (size_t j = i; j < total; j += stride) g_agg[j] = 0.0f;
    for (size_t j = i; j < NNODES; j += stride) g_denom[j] = 0.0f;
}

// ---------------------------------------------------------------------------
// One-pass scatter attention: one warp per occurrence.
// score = dot(enc, q[node]) / 16 ; w = exp(score) (no max-subtraction needed:
// softmax is shift invariant and scores are O(1), exp cannot overflow fp32).
// Accumulate w*enc into g_agg and w into g_denom with global reductions.
// ---------------------------------------------------------------------------
__global__ __launch_bounds__(256)
void scatter_kernel(const float* __restrict__ enc,
                    const void* __restrict__ mask,
                    const int* __restrict__ idx) {
    int occ  = (int)((blockIdx.x * blockDim.x + threadIdx.x) >> 5);
    int lane = threadIdx.x & 31;
    if (occ >= PL_TOTAL) return;

    bool live;
    if (g_mask_word)
        live = ((const unsigned int*)mask)[occ] != 0u;   // f32 or i32: bits!=0
    else
        live = ((const unsigned char*)mask)[occ] != 0;
    if (!live) return;                    // masked -> weight exactly 0, skip

    int node = idx[occ];
    const float4* e4 = (const float4*)(enc + (size_t)occ * DIM);
    const float4* q4 = (const float4*)(g_q + (size_t)node * DIM);

    float4 e0 = e4[lane];
    float4 e1 = e4[lane + 32];
    float4 q0 = q4[lane];
    float4 q1 = q4[lane + 32];

    float p = e0.x * q0.x + e0.y * q0.y + e0.z * q0.z + e0.w * q0.w
            + e1.x * q1.x + e1.y * q1.y + e1.z * q1.z + e1.w * q1.w;
#pragma unroll
    for (int o = 16; o; o >>= 1) p += __shfl_xor_sync(0xffffffffu, p, o);

    float w = __expf(p * 0.0625f);        // 1/sqrt(256) = 1/16

    float* base = g_agg + (size_t)node * DIM;
    float4 v0 = make_float4(w * e0.x, w * e0.y, w * e0.z, w * e0.w);
    float4 v1 = make_float4(w * e1.x, w * e1.y, w * e1.z, w * e1.w);

    asm volatile("red.global.add.v4.f32 [%0], {%1,%2,%3,%4};"
                 :: "l"(base + lane * 4),
                    "f"(v0.x), "f"(v0.y), "f"(v0.z), "f"(v0.w) : "memory");
    asm volatile("red.global.add.v4.f32 [%0], {%1,%2,%3,%4};"
                 :: "l"(base + 128 + lane * 4),
                    "f"(v1.x), "f"(v1.y), "f"(v1.z), "f"(v1.w) : "memory");

    if (lane == 0) atomicAdd(&g_denom[node], w);
}

// ---------------------------------------------------------------------------
// agg[n, :] /= (denom[n] + 1e-9)
// ---------------------------------------------------------------------------
__global__ __launch_bounds__(256)
void normalize_kernel() {
    size_t i = (size_t)blockIdx.x * blockDim.x + threadIdx.x;
    size_t total4 = (size_t)NNODES * DIM / 4;
    if (i >= total4) return;
    int row = (int)(i >> 6);              // 64 float4 per row
    float rd = 1.0f / (g_denom[row] + 1e-9f);
    float4* p = ((float4*)g_agg) + i;
    float4 v = *p;
    v.x *= rd; v.y *= rd; v.z *= rd; v.w *= rd;
    *p = v;
}

// ---------------------------------------------------------------------------
// Tiled SGEMM: C[M,256] = [A1 | A2] @ W (+bias), optional fused sigmoid-gate
// epilogue: out = z*A1 + (1-z)*A2 with z = sigmoid(S).
// Tile 128x128, BK=8, 256 threads, 8x8 per-thread microtile (split 4+4).
// ---------------------------------------------------------------------------
template <int KTOT, bool FUSE>
__global__ __launch_bounds__(256)
void sgemm_kernel(const float* __restrict__ A1,   // [M,256]
                  const float* __restrict__ A2,   // [M,256] (KTOT==512 / FUSE)
                  const float* __restrict__ W,    // [KTOT,256]
                  const float* __restrict__ bias, // [256] or null
                  float* __restrict__ C,          // [M,256]
                  int M) {
    __shared__ float As[8][128];
    __shared__ float Bs[8][128];

    const int tid = threadIdx.x;
    const int bm = blockIdx.x * 128;
    const int bn = blockIdx.y * 128;
    const int ty = tid >> 4;         // 0..15
    const int tx = tid & 15;         // 0..15

    // loader indices
    const int ar = tid >> 1;               // A row within tile (0..127)
    const int ac = (tid & 1) * 4;          // A k-offset (0 or 4)
    const int br = tid >> 5;               // B k row (0..7)
    const int bc = (tid & 31) * 4;         // B col (0..124)

    float acc[8][8];
#pragma unroll
    for (int i = 0; i < 8; i++)
#pragma unroll
        for (int j = 0; j < 8; j++) acc[i][j] = 0.0f;

    for (int k0 = 0; k0 < KTOT; k0 += 8) {
        const float* Asrc = (KTOT == 512 && k0 >= 256) ? A2 : A1;
        const int kloc = k0 & 255;

        float4 av = make_float4(0.f, 0.f, 0.f, 0.f);
        int grow = bm + ar;
        if (grow < M)
            av = *(const float4*)(Asrc + (size_t)grow * 256 + kloc + ac);
        As[ac + 0][ar] = av.x;
        As[ac + 1][ar] = av.y;
        As[ac + 2][ar] = av.z;
        As[ac + 3][ar] = av.w;

        float4 bv = *(const float4*)(W + (size_t)(k0 + br) * 256 + bn + bc);
        *(float4*)&Bs[br][bc] = bv;

        __syncthreads();

#pragma unroll
        for (int kk = 0; kk < 8; kk++) {
            float a[8], b[8];
            *(float4*)&a[0] = *(const float4*)&As[kk][ty * 4];
            *(float4*)&a[4] = *(const float4*)&As[kk][64 + ty * 4];
            *(float4*)&b[0] = *(const float4*)&Bs[kk][tx * 4];
            *(float4*)&b[4] = *(const float4*)&Bs[kk][64 + tx * 4];
#pragma unroll
            for (int i = 0; i < 8; i++)
#pragma unroll
                for (int j = 0; j < 8; j++) acc[i][j] += a[i] * b[j];
        }
        __syncthreads();
    }

    // epilogue
#pragma unroll
    for (int i = 0; i < 8; i++) {
        int m = bm + ((i < 4) ? (ty * 4 + i) : (64 + ty * 4 + i - 4));
        if (m >= M) continue;
#pragma unroll
        for (int g = 0; g < 2; g++) {
            int n = bn + ((g == 0) ? (tx * 4) : (64 + tx * 4));
            if (FUSE) {
                float4 bb = *(const float4*)(bias + n);
                float4 pv = *(const float4*)(A1 + (size_t)m * 256 + n);
                float4 ag = *(const float4*)(A2 + (size_t)m * 256 + n);
                float s0 = acc[i][g * 4 + 0] + bb.x;
                float s1 = acc[i][g * 4 + 1] + bb.y;
                float s2 = acc[i][g * 4 + 2] + bb.z;
                float s3 = acc[i][g * 4 + 3] + bb.w;
                float z0 = 1.0f / (1.0f + __expf(-s0));
                float z1 = 1.0f / (1.0f + __expf(-s1));
                float z2 = 1.0f / (1.0f + __expf(-s2));
                float z3 = 1.0f / (1.0f + __expf(-s3));
                float4 o;
                o.x = z0 * pv.x + (1.0f - z0) * ag.x;
                o.y = z1 * pv.y + (1.0f - z1) * ag.y;
                o.z = z2 * pv.z + (1.0f - z2) * ag.z;
                o.w = z3 * pv.w + (1.0f - z3) * ag.w;
                *(float4*)(C + (size_t)m * 256 + n) = o;
            } else {
                float4 o;
                o.x = acc[i][g * 4 + 0];
                o.y = acc[i][g * 4 + 1];
                o.z = acc[i][g * 4 + 2];
                o.w = acc[i][g * 4 + 3];
                *(float4*)(C + (size_t)m * 256 + n) = o;
            }
        }
    }
}

// ---------------------------------------------------------------------------
// Launch
// Inputs (metadata order): 0 encoded_paths f32 [2048,256,256],
// 1 paths_mask (bool/f32/i32 -- autodetected) [2048,256],
// 2 paths_node_indices i32 [2048,256], 3 previous_encodings f32 [50000,256],
// 4 Wq f32 [256,256], 5 Wg f32 [512,256], 6 bg f32 [256], 7 nr_cfg_nodes
// ---------------------------------------------------------------------------
extern "C" void kernel_launch(void* const* d_in, const int* in_sizes, int n_in,
                              void* d_out, int out_size) {
    const float* enc          = (const float*)d_in[0];
    const void*  mask         = d_in[1];
    const int* idx            = (const int*)d_in[2];
    const float* prev         = (const float*)d_in[3];
    const float* Wq           = (const float*)d_in[4];
    const float* Wg           = (const float*)d_in[5];
    const float* bg           = (const float*)d_in[6];
    float* out                = (float*)d_out;

    void *qp = nullptr, *aggp = nullptr;
    cudaGetSymbolAddress(&qp, g_q);
    cudaGetSymbolAddress(&aggp, g_agg);
    float* q_buf   = (float*)qp;
    float* agg_buf = (float*)aggp;

    const int M = NNODES;

    // 0) detect mask element width
    detect_mask_kernel<<<1, 256>>>((const unsigned char*)mask);

    // 1) zero accumulators
    zero_kernel<<<2048, 256>>>();

    // 2) q = prev @ Wq
    {
        dim3 grid((M + 127) / 128, 2);
        sgemm_kernel<256, false><<<grid, 256>>>(prev, prev, Wq, nullptr, q_buf, M);
    }

    // 3) one-pass scatter softmax-numerator/denominator
    scatter_kernel<<<PL_TOTAL / 8, 256>>>(enc, mask, idx);

    // 4) normalize agg
    {
        size_t total4 = (size_t)NNODES * DIM / 4;
        normalize_kernel<<<(unsigned)((total4 + 255) / 256), 256>>>();
    }

    // 5) gated update: out = z*prev + (1-z)*agg, z = sigmoid([prev|agg]@Wg+bg)
    {
        dim3 grid((M + 127) / 128, 2);
        sgemm_kernel<512, true><<<grid, 256>>>(prev, agg_buf, Wg, bg, out, M);
    }
}